// round 4
// baseline (speedup 1.0000x reference)
#include <cuda_runtime.h>
#include <cuda_bf16.h>
#include <math.h>

// Problem constants
#define BB   4
#define CINE 256
#define CIN  1024
#define CO   256
#define HW   16384        // H*W = 128*128
#define CQ   32
#define NPOS 16384.0f

typedef unsigned long long u64;

// Scratch (device globals -- no runtime allocation allowed)
__device__ float g_x[(size_t)BB * CO * HW];   // raw conv output (pre-BN)
__device__ float g_v[(size_t)BB * CO * HW];   // V
__device__ float g_q[BB * CQ * HW];           // Q then Qn
__device__ float g_k[BB * CQ * HW];           // K then Kn
__device__ float g_mean[CO];
__device__ float g_invstd[CO];
__device__ float g_ksum[BB * CQ];
__device__ float g_vsum[BB * CO];
__device__ float g_matrix[BB * CQ * CO];

__device__ __forceinline__ float fixnum(float r) {
    if (isnan(r)) return 0.0f;
    if (isinf(r)) return r > 0.0f ? 1.0f : -1.0f;
    return r;
}

// packed fp32x2 FMA: d = a*b + d (lanewise on the two 32-bit halves)
__device__ __forceinline__ void ffma2(u64& d, u64 a, u64 b) {
    asm("fma.rn.f32x2 %0, %1, %2, %0;" : "+l"(d) : "l"(a), "l"(b));
}

// ---------------------------------------------------------------------------
__global__ void zero_kernel() {
    int tid = blockIdx.x * blockDim.x + threadIdx.x;
    int total = BB * CQ + BB * CQ * CO;
    for (int i = tid; i < total; i += gridDim.x * blockDim.x) {
        if (i < BB * CQ) g_ksum[i] = 0.0f;
        else g_matrix[i - BB * CQ] = 0.0f;
    }
}

// ---------------------------------------------------------------------------
// 1x1 conv GEMM with packed f32x2 FMAs.
// g_x[b,m,n] = sum_c w[m,c] * fcat[b,c,n]
// 128x128 tile, BK=8, 256 threads, 8x8 microtile held as 8x4 f32x2 pairs.
__global__ __launch_bounds__(256) void conv_gemm(
    const float* __restrict__ s5, const float* __restrict__ s4,
    const float* __restrict__ s3, const float* __restrict__ s2,
    const float* __restrict__ w)
{
    const int b  = blockIdx.z;
    const int m0 = blockIdx.y * 128;
    const int n0 = blockIdx.x * 128;

    __shared__ float2 sA[8][128];   // pre-duplicated A pairs {w,w}
    __shared__ float  sB[8][128];

    const int t  = threadIdx.x;
    const int tx = t % 16;
    const int ty = t / 16;

    const int arow = t >> 1;
    const int akq  = (t & 1) * 4;
    const int bkk = t >> 5;
    const int bnq = (t & 31) * 4;

    u64 acc[8][4];
#pragma unroll
    for (int i = 0; i < 8; i++)
#pragma unroll
        for (int j = 0; j < 4; j++) acc[i][j] = 0ull;

    for (int k0 = 0; k0 < CIN; k0 += 8) {
        // A (w_conv) -> shared, transposed to [k][m], duplicated into pairs
        float4 a4 = *(const float4*)(w + (size_t)(m0 + arow) * CIN + k0 + akq);
        sA[akq + 0][arow] = make_float2(a4.x, a4.x);
        sA[akq + 1][arow] = make_float2(a4.y, a4.y);
        sA[akq + 2][arow] = make_float2(a4.z, a4.z);
        sA[akq + 3][arow] = make_float2(a4.w, a4.w);

        // B (concatenated inputs)
        int ch = k0 + bkk;
        const float* src = (ch < 512) ? (ch < 256 ? s5 : s4)
                                      : (ch < 768 ? s3 : s2);
        float4 b4 = *(const float4*)(src + (size_t)(b * CINE + (ch & 255)) * HW + n0 + bnq);
        *(float4*)&sB[bkk][bnq] = b4;

        __syncthreads();

#pragma unroll
        for (int kk = 0; kk < 8; kk++) {
            u64 ra[8], rb[4];
#pragma unroll
            for (int i = 0; i < 8; i++)
                ra[i] = *(const u64*)&sA[kk][ty * 8 + i];
#pragma unroll
            for (int j = 0; j < 4; j++)
                rb[j] = *(const u64*)&sB[kk][tx * 8 + j * 2];
#pragma unroll
            for (int i = 0; i < 8; i++)
#pragma unroll
                for (int j = 0; j < 4; j++)
                    ffma2(acc[i][j], ra[i], rb[j]);
        }
        __syncthreads();
    }

#pragma unroll
    for (int i = 0; i < 8; i++) {
        int m = m0 + ty * 8 + i;
        float* dst = g_x + (size_t)(b * CO + m) * HW + n0 + tx * 8;
        const float* accf = (const float*)acc[i];
        *(float4*)(dst + 0) = make_float4(accf[0], accf[1], accf[2], accf[3]);
        *(float4*)(dst + 4) = make_float4(accf[4], accf[5], accf[6], accf[7]);
    }
}

// ---------------------------------------------------------------------------
// BN statistics over raw conv output: one block per channel
__global__ __launch_bounds__(512) void bn_stats() {
    const int co = blockIdx.x;
    const int tid = threadIdx.x;
    float s = 0.0f, ss = 0.0f;
    for (int b = 0; b < BB; b++) {
        const float* p = g_x + (size_t)(b * CO + co) * HW;
        for (int i = tid; i < HW; i += 512) {
            float v = p[i];
            s += v;
            ss += v * v;
        }
    }
    __shared__ float rs[512], rss[512];
    rs[tid] = s; rss[tid] = ss;
    __syncthreads();
    for (int off = 256; off > 0; off >>= 1) {
        if (tid < off) { rs[tid] += rs[tid + off]; rss[tid] += rss[tid + off]; }
        __syncthreads();
    }
    if (tid == 0) {
        const float cnt = (float)(BB * HW);
        float mean = rs[0] / cnt;
        float var  = rss[0] / cnt - mean * mean;
        g_mean[co]   = mean;
        g_invstd[co] = rsqrtf(var + 1e-5f);
    }
}

// ---------------------------------------------------------------------------
// Fused QKV GEMM (f32x2) with BN-affine + ReLU applied to the B tile on load.
// rows 0..31 = Q, 32..63 = K, 64..319 = V. K-dim = 256 feat channels.
__global__ __launch_bounds__(256) void qkv_gemm(
    const float* __restrict__ wq, const float* __restrict__ bq,
    const float* __restrict__ wk, const float* __restrict__ bk,
    const float* __restrict__ wv, const float* __restrict__ bv,
    const float* __restrict__ bn_gamma, const float* __restrict__ bn_beta)
{
    const int b  = blockIdx.z;
    const int m0 = blockIdx.y * 128;
    const int n0 = blockIdx.x * 128;

    __shared__ float2 sA[8][128];
    __shared__ float  sB[8][128];

    const int t  = threadIdx.x;
    const int tx = t % 16;
    const int ty = t / 16;
    const int arow = t >> 1;
    const int akq  = (t & 1) * 4;
    const int bkk = t >> 5;
    const int bnq = (t & 31) * 4;

    u64 acc[8][4];
#pragma unroll
    for (int i = 0; i < 8; i++)
#pragma unroll
        for (int j = 0; j < 4; j++) acc[i][j] = 0ull;

    for (int k0 = 0; k0 < CO; k0 += 8) {
        int m = m0 + arow;
        float4 a4 = make_float4(0.f, 0.f, 0.f, 0.f);
        if (m < 320) {
            const float* wrow;
            if (m < 32)       wrow = wq + (size_t)m * CO;
            else if (m < 64)  wrow = wk + (size_t)(m - 32) * CO;
            else              wrow = wv + (size_t)(m - 64) * CO;
            a4 = *(const float4*)(wrow + k0 + akq);
        }
        sA[akq + 0][arow] = make_float2(a4.x, a4.x);
        sA[akq + 1][arow] = make_float2(a4.y, a4.y);
        sA[akq + 2][arow] = make_float2(a4.z, a4.z);
        sA[akq + 3][arow] = make_float2(a4.w, a4.w);

        int ch = k0 + bkk;
        float scale = g_invstd[ch] * bn_gamma[ch];
        float shift = bn_beta[ch] - g_mean[ch] * scale;
        float4 b4 = *(const float4*)(g_x + (size_t)(b * CO + ch) * HW + n0 + bnq);
        b4.x = fmaxf(b4.x * scale + shift, 0.0f);
        b4.y = fmaxf(b4.y * scale + shift, 0.0f);
        b4.z = fmaxf(b4.z * scale + shift, 0.0f);
        b4.w = fmaxf(b4.w * scale + shift, 0.0f);
        *(float4*)&sB[bkk][bnq] = b4;

        __syncthreads();
#pragma unroll
        for (int kk = 0; kk < 8; kk++) {
            u64 ra[8], rb[4];
#pragma unroll
            for (int i = 0; i < 8; i++)
                ra[i] = *(const u64*)&sA[kk][ty * 8 + i];
#pragma unroll
            for (int j = 0; j < 4; j++)
                rb[j] = *(const u64*)&sB[kk][tx * 8 + j * 2];
#pragma unroll
            for (int i = 0; i < 8; i++)
#pragma unroll
                for (int j = 0; j < 4; j++)
                    ffma2(acc[i][j], ra[i], rb[j]);
        }
        __syncthreads();
    }

#pragma unroll
    for (int i = 0; i < 8; i++) {
        int m = m0 + ty * 8 + i;
        if (m >= 320) continue;
        float bias;
        float* dst;
        if (m < 32)      { bias = bq[m];      dst = g_q + (size_t)(b * CQ + m) * HW; }
        else if (m < 64) { bias = bk[m - 32]; dst = g_k + (size_t)(b * CQ + m - 32) * HW; }
        else             { bias = bv[m - 64]; dst = g_v + (size_t)(b * CO + m - 64) * HW; }
        float* p = dst + n0 + tx * 8;
        const float* accf = (const float*)acc[i];
        *(float4*)(p + 0) = make_float4(accf[0] + bias, accf[1] + bias,
                                        accf[2] + bias, accf[3] + bias);
        *(float4*)(p + 4) = make_float4(accf[4] + bias, accf[5] + bias,
                                        accf[6] + bias, accf[7] + bias);
    }
}

// ---------------------------------------------------------------------------
// L2-normalize Q and K over channels per position, accumulate Ksum
__global__ __launch_bounds__(256) void normalize_qk() {
    const int b = blockIdx.y;
    const int n = blockIdx.x * 256 + threadIdx.x;
    const int lane = threadIdx.x & 31;

    {
        float q[CQ];
        float s = 0.0f;
#pragma unroll
        for (int c = 0; c < CQ; c++) {
            q[c] = g_q[(size_t)(b * CQ + c) * HW + n];
            s += q[c] * q[c];
        }
        float sc = 1.0f / fmaxf(sqrtf(s), 1e-6f);
#pragma unroll
        for (int c = 0; c < CQ; c++)
            g_q[(size_t)(b * CQ + c) * HW + n] = q[c] * sc;
    }
    {
        float k[CQ];
        float s = 0.0f;
#pragma unroll
        for (int c = 0; c < CQ; c++) {
            k[c] = g_k[(size_t)(b * CQ + c) * HW + n];
            s += k[c] * k[c];
        }
        float sc = 1.0f / fmaxf(sqrtf(s), 1e-6f);
#pragma unroll
        for (int c = 0; c < CQ; c++) {
            float v = k[c] * sc;
            g_k[(size_t)(b * CQ + c) * HW + n] = v;
            float r = v;
#pragma unroll
            for (int off = 16; off > 0; off >>= 1)
                r += __shfl_down_sync(0xffffffffu, r, off);
            if (lane == 0) atomicAdd(&g_ksum[b * CQ + c], r);
        }
    }
}

// ---------------------------------------------------------------------------
__global__ __launch_bounds__(256) void vsum_kernel() {
    const int c = blockIdx.x;
    const int b = blockIdx.y;
    const int tid = threadIdx.x;
    const float* p = g_v + (size_t)(b * CO + c) * HW;
    float s = 0.0f;
    for (int i = tid; i < HW; i += 256) s += p[i];
    __shared__ float rs[256];
    rs[tid] = s;
    __syncthreads();
    for (int off = 128; off > 0; off >>= 1) {
        if (tid < off) rs[tid] += rs[tid + off];
        __syncthreads();
    }
    if (tid == 0) g_vsum[b * CO + c] = rs[0];
}

// ---------------------------------------------------------------------------
// matrix[b,q,c] = sum_n Kn[b,q,n] * V[b,c,n]  (split-K over n, atomic reduce)
__global__ __launch_bounds__(256) void matrix_kernel() {
    const int b   = blockIdx.z;
    const int c0  = blockIdx.y * 64;
    const int nb0 = blockIdx.x * 512;

    __shared__ float sK[CQ][65];
    __shared__ float sV[64][65];

    const int t  = threadIdx.x;
    const int c  = t & 63;
    const int qg = t >> 6;

    float acc[8];
#pragma unroll
    for (int i = 0; i < 8; i++) acc[i] = 0.0f;

    for (int nb = nb0; nb < nb0 + 512; nb += 64) {
#pragma unroll
        for (int i = 0; i < 8; i++) {
            int idx = t + i * 256;
            int q = idx >> 6, j = idx & 63;
            sK[q][j] = g_k[(size_t)(b * CQ + q) * HW + nb + j];
        }
#pragma unroll
        for (int i = 0; i < 16; i++) {
            int idx = t + i * 256;
            int cc = idx >> 6, j = idx & 63;
            sV[cc][j] = g_v[(size_t)(b * CO + c0 + cc) * HW + nb + j];
        }
        __syncthreads();
#pragma unroll 8
        for (int j = 0; j < 64; j++) {
            float vv = sV[c][j];
#pragma unroll
            for (int i = 0; i < 8; i++)
                acc[i] += sK[qg * 8 + i][j] * vv;
        }
        __syncthreads();
    }
#pragma unroll
    for (int i = 0; i < 8; i++)
        atomicAdd(&g_matrix[(size_t)(b * CQ + qg * 8 + i) * CO + c0 + c], acc[i]);
}

// ---------------------------------------------------------------------------
// Final: out = nan_to_num(gamma * (Vsum + Qn^T matrix) * tailor) + feat
// feat = relu(bn(g_x)) computed inline.
__global__ __launch_bounds__(128) void final_kernel(
    const float* __restrict__ gamma_p,
    const float* __restrict__ bn_gamma, const float* __restrict__ bn_beta,
    float* __restrict__ out)
{
    const int b = blockIdx.y;
    const int n = blockIdx.x * 128 + threadIdx.x;
    const int tid = threadIdx.x;

    __shared__ float sM[CQ][CO];   // 32 KB
    __shared__ float sVs[CO];
    __shared__ float sKs[CQ];
    __shared__ float sScale[CO];
    __shared__ float sShift[CO];

#pragma unroll
    for (int i = 0; i < 64; i++) {
        int idx = tid + i * 128;
        ((float*)sM)[idx] = g_matrix[(size_t)b * CQ * CO + idx];
    }
#pragma unroll
    for (int r = 0; r < 2; r++) {
        int c = tid + r * 128;
        sVs[c] = g_vsum[b * CO + c];
        float scale = g_invstd[c] * bn_gamma[c];
        sScale[c] = scale;
        sShift[c] = bn_beta[c] - g_mean[c] * scale;
    }
    if (tid < CQ) sKs[tid] = g_ksum[b * CQ + tid];
    __syncthreads();

    float qn[CQ];
    float e = 0.0f;
#pragma unroll
    for (int q = 0; q < CQ; q++) {
        qn[q] = g_q[(size_t)(b * CQ + q) * HW + n];
        e += qn[q] * sKs[q];
    }
    const float tailor = 1.0f / fmaxf(NPOS + e, 1e-6f);
    const float gm = *gamma_p;

    for (int c0 = 0; c0 < CO; c0 += 4) {
        float4 a = *(const float4*)&sVs[c0];
#pragma unroll
        for (int q = 0; q < CQ; q++) {
            float4 m4 = *(const float4*)&sM[q][c0];
            a.x += qn[q] * m4.x;
            a.y += qn[q] * m4.y;
            a.z += qn[q] * m4.z;
            a.w += qn[q] * m4.w;
        }
        float r0 = fixnum(gm * a.x * tailor);
        float r1 = fixnum(gm * a.y * tailor);
        float r2 = fixnum(gm * a.z * tailor);
        float r3 = fixnum(gm * a.w * tailor);
        size_t base = (size_t)(b * CO + c0) * HW + n;
        float f0 = fmaxf(g_x[base + 0 * HW] * sScale[c0 + 0] + sShift[c0 + 0], 0.0f);
        float f1 = fmaxf(g_x[base + 1 * HW] * sScale[c0 + 1] + sShift[c0 + 1], 0.0f);
        float f2 = fmaxf(g_x[base + 2 * HW] * sScale[c0 + 2] + sShift[c0 + 2], 0.0f);
        float f3 = fmaxf(g_x[base + 3 * HW] * sScale[c0 + 3] + sShift[c0 + 3], 0.0f);
        out[base + 0 * HW] = r0 + f0;
        out[base + 1 * HW] = r1 + f1;
        out[base + 2 * HW] = r2 + f2;
        out[base + 3 * HW] = r3 + f3;
    }
}

// ---------------------------------------------------------------------------
extern "C" void kernel_launch(void* const* d_in, const int* in_sizes, int n_in,
                              void* d_out, int out_size)
{
    const float* s5 = (const float*)d_in[0];
    const float* s4 = (const float*)d_in[1];
    const float* s3 = (const float*)d_in[2];
    const float* s2 = (const float*)d_in[3];
    const float* w_conv   = (const float*)d_in[4];
    const float* bn_gamma = (const float*)d_in[5];
    const float* bn_beta  = (const float*)d_in[6];
    const float* wq = (const float*)d_in[7];
    const float* bq = (const float*)d_in[8];
    const float* wk = (const float*)d_in[9];
    const float* bk = (const float*)d_in[10];
    const float* wv = (const float*)d_in[11];
    const float* bv = (const float*)d_in[12];
    const float* gamma = (const float*)d_in[13];
    float* out = (float*)d_out;

    zero_kernel<<<64, 256>>>();
    conv_gemm<<<dim3(HW / 128, CO / 128, BB), 256>>>(s5, s4, s3, s2, w_conv);
    bn_stats<<<CO, 512>>>();
    qkv_gemm<<<dim3(HW / 128, 3, BB), 256>>>(wq, bq, wk, bk, wv, bv, bn_gamma, bn_beta);
    normalize_qk<<<dim3(HW / 256, BB), 256>>>();
    vsum_kernel<<<dim3(CO, BB), 256>>>();
    matrix_kernel<<<dim3(32, CO / 64, BB), 256>>>();
    final_kernel<<<dim3(HW / 128, BB), 128>>>(gamma, bn_gamma, bn_beta, out);
}

// round 9
// speedup vs baseline: 2.1067x; 2.1067x over previous
#include <cuda_runtime.h>
#include <cuda_bf16.h>
#include <math.h>
#include <stdint.h>

// Problem constants
#define BB   4
#define CINE 256
#define CIN  1024
#define CO   256
#define HW   16384        // H*W = 128*128
#define CQ   32
#define NPOS 16384.0f

#define AK 18             // padded bf16 row length (16 + 2) => 36B rows

// Scratch (device globals -- no runtime allocation allowed)
__device__ float g_x[(size_t)BB * CO * HW];   // raw conv output (pre-BN)
__device__ float g_v[(size_t)BB * CO * HW];   // V
__device__ float g_q[BB * CQ * HW];           // Q then Qn
__device__ float g_k[BB * CQ * HW];           // K then Kn
__device__ float g_mean[CO];
__device__ float g_invstd[CO];
__device__ float g_ksum[BB * CQ];
__device__ float g_vsum[BB * CO];
__device__ float g_matrix[BB * CQ * CO];

__device__ __forceinline__ float fixnum(float r) {
    if (isnan(r)) return 0.0f;
    if (isinf(r)) return r > 0.0f ? 1.0f : -1.0f;
    return r;
}

// hi/lo bf16 split of two floats, packed as bf16x2 (x -> low 16 bits)
__device__ __forceinline__ void split_pack(float x, float y, uint32_t& h, uint32_t& l) {
    __nv_bfloat162 hb = __floats2bfloat162_rn(x, y);
    h = *reinterpret_cast<uint32_t*>(&hb);
    float rx = x - __bfloat162float(hb.x);
    float ry = y - __bfloat162float(hb.y);
    __nv_bfloat162 lb = __floats2bfloat162_rn(rx, ry);
    l = *reinterpret_cast<uint32_t*>(&lb);
}

// m16n8k16 row.col bf16 MMA, f32 accumulate in-place
__device__ __forceinline__ void mma16816(float* c,
    uint32_t a0, uint32_t a1, uint32_t a2, uint32_t a3,
    uint32_t b0, uint32_t b1)
{
    asm volatile(
        "mma.sync.aligned.m16n8k16.row.col.f32.bf16.bf16.f32 "
        "{%0,%1,%2,%3}, {%4,%5,%6,%7}, {%8,%9}, {%0,%1,%2,%3};"
        : "+f"(c[0]), "+f"(c[1]), "+f"(c[2]), "+f"(c[3])
        : "r"(a0), "r"(a1), "r"(a2), "r"(a3), "r"(b0), "r"(b1));
}

// ---------------------------------------------------------------------------
__global__ void zero_kernel() {
    int tid = blockIdx.x * blockDim.x + threadIdx.x;
    int total = BB * CQ + BB * CQ * CO;
    for (int i = tid; i < total; i += gridDim.x * blockDim.x) {
        if (i < BB * CQ) g_ksum[i] = 0.0f;
        else g_matrix[i - BB * CQ] = 0.0f;
    }
}

// ---------------------------------------------------------------------------
// conv 1x1 as bf16-split mma.sync GEMM: g_x[b,m,n] = sum_c w[m,c]*fcat[b,c,n]
// CTA tile 128x128, K chunk = 16 fp32 channels, 3 bf16 passes per chunk.
__global__ __launch_bounds__(256) void conv_gemm_mma(
    const float* __restrict__ s5, const float* __restrict__ s4,
    const float* __restrict__ s3, const float* __restrict__ s2,
    const float* __restrict__ w)
{
    __shared__ unsigned short sAh[128][AK], sAl[128][AK];
    __shared__ unsigned short sBh[128][AK], sBl[128][AK];
    __shared__ float sStage[16][128];

    const int t = threadIdx.x;
    const int wid = t >> 5, lane = t & 31;
    const int g = lane >> 2, tg = lane & 3;
    const int b = blockIdx.z, m0 = blockIdx.y * 128, n0 = blockIdx.x * 128;
    const int wm = (wid & 1) * 64, wn = (wid >> 1) * 32;

    // loader indices
    const int ar = t >> 1,  ak  = (t & 1) * 8;    // A: row m0+ar, k offset ak..ak+7
    const int bc = t >> 4,  bn4 = (t & 15) * 8;   // B: ch k0+bc, cols n0+bn4..+7
    const int tn = t & 127, tk  = (t >> 7) * 8;   // transpose: n=tn, k=tk..tk+7

    float acc[4][4][4];
#pragma unroll
    for (int i = 0; i < 4; i++)
#pragma unroll
        for (int j = 0; j < 4; j++)
#pragma unroll
            for (int r = 0; r < 4; r++) acc[i][j][r] = 0.0f;

    const float* wA = w + (size_t)(m0 + ar) * CIN + ak;

    // prefetch iter 0
    float4 pA0, pA1, pB0, pB1;
    {
        pA0 = *(const float4*)(wA + 0);
        pA1 = *(const float4*)(wA + 4);
        int ch = bc;
        const float* src = (ch < 512) ? (ch < 256 ? s5 : s4) : (ch < 768 ? s3 : s2);
        const float* pB = src + (size_t)(b * CINE + (ch & 255)) * HW + n0 + bn4;
        pB0 = *(const float4*)(pB + 0);
        pB1 = *(const float4*)(pB + 4);
    }

    for (int it = 0; it < CIN / 16; it++) {
        __syncthreads();   // previous iter's mma reads are done
        // store A split (already K-major rows)
        {
            uint32_t h, l;
            split_pack(pA0.x, pA0.y, h, l);
            *(uint32_t*)&sAh[ar][ak + 0] = h; *(uint32_t*)&sAl[ar][ak + 0] = l;
            split_pack(pA0.z, pA0.w, h, l);
            *(uint32_t*)&sAh[ar][ak + 2] = h; *(uint32_t*)&sAl[ar][ak + 2] = l;
            split_pack(pA1.x, pA1.y, h, l);
            *(uint32_t*)&sAh[ar][ak + 4] = h; *(uint32_t*)&sAl[ar][ak + 4] = l;
            split_pack(pA1.z, pA1.w, h, l);
            *(uint32_t*)&sAh[ar][ak + 6] = h; *(uint32_t*)&sAl[ar][ak + 6] = l;
        }
        // store B fp32 stage
        *(float4*)&sStage[bc][bn4 + 0] = pB0;
        *(float4*)&sStage[bc][bn4 + 4] = pB1;
        __syncthreads();
        // transpose + split B -> [n][k]
#pragma unroll
        for (int j = 0; j < 8; j += 2) {
            float v0 = sStage[tk + j][tn];
            float v1 = sStage[tk + j + 1][tn];
            uint32_t h, l;
            split_pack(v0, v1, h, l);
            *(uint32_t*)&sBh[tn][tk + j] = h;
            *(uint32_t*)&sBl[tn][tk + j] = l;
        }
        __syncthreads();
        // prefetch next iter (overlaps with mma below)
        if (it + 1 < CIN / 16) {
            int k0n = (it + 1) * 16;
            pA0 = *(const float4*)(wA + k0n);
            pA1 = *(const float4*)(wA + k0n + 4);
            int ch = k0n + bc;
            const float* src = (ch < 512) ? (ch < 256 ? s5 : s4) : (ch < 768 ? s3 : s2);
            const float* pB = src + (size_t)(b * CINE + (ch & 255)) * HW + n0 + bn4;
            pB0 = *(const float4*)(pB + 0);
            pB1 = *(const float4*)(pB + 4);
        }
        // 3 bf16 passes: (Ah,Bh), (Ah,Bl), (Al,Bh)
#pragma unroll
        for (int pass = 0; pass < 3; pass++) {
            const unsigned short (*A)[AK] = (pass == 2) ? sAl : sAh;
            const unsigned short (*B)[AK] = (pass == 1) ? sBl : sBh;
            uint32_t bf[4][2];
#pragma unroll
            for (int nt = 0; nt < 4; nt++) {
                bf[nt][0] = *(const uint32_t*)&B[wn + nt * 8 + g][2 * tg];
                bf[nt][1] = *(const uint32_t*)&B[wn + nt * 8 + g][2 * tg + 8];
            }
#pragma unroll
            for (int mt = 0; mt < 4; mt++) {
                uint32_t a0 = *(const uint32_t*)&A[wm + mt * 16 + g][2 * tg];
                uint32_t a1 = *(const uint32_t*)&A[wm + mt * 16 + g + 8][2 * tg];
                uint32_t a2 = *(const uint32_t*)&A[wm + mt * 16 + g][2 * tg + 8];
                uint32_t a3 = *(const uint32_t*)&A[wm + mt * 16 + g + 8][2 * tg + 8];
#pragma unroll
                for (int nt = 0; nt < 4; nt++)
                    mma16816(acc[mt][nt], a0, a1, a2, a3, bf[nt][0], bf[nt][1]);
            }
        }
    }

    // writeback
#pragma unroll
    for (int mt = 0; mt < 4; mt++) {
        int m = m0 + wm + mt * 16 + g;
        float* base = g_x + (size_t)(b * CO + m) * HW + n0 + wn + 2 * tg;
#pragma unroll
        for (int nt = 0; nt < 4; nt++) {
            float* p = base + nt * 8;
            *(float2*)p = make_float2(acc[mt][nt][0], acc[mt][nt][1]);
            *(float2*)(p + 8 * HW) = make_float2(acc[mt][nt][2], acc[mt][nt][3]);
        }
    }
}

// ---------------------------------------------------------------------------
// BN statistics over raw conv output: one block per channel
__global__ __launch_bounds__(512) void bn_stats() {
    const int co = blockIdx.x;
    const int tid = threadIdx.x;
    float s = 0.0f, ss = 0.0f;
    for (int b = 0; b < BB; b++) {
        const float* p = g_x + (size_t)(b * CO + co) * HW;
        for (int i = tid; i < HW; i += 512) {
            float v = p[i];
            s += v;
            ss += v * v;
        }
    }
    __shared__ float rs[512], rss[512];
    rs[tid] = s; rss[tid] = ss;
    __syncthreads();
    for (int off = 256; off > 0; off >>= 1) {
        if (tid < off) { rs[tid] += rs[tid + off]; rss[tid] += rss[tid + off]; }
        __syncthreads();
    }
    if (tid == 0) {
        const float cnt = (float)(BB * HW);
        float mean = rs[0] / cnt;
        float var  = rss[0] / cnt - mean * mean;
        g_mean[co]   = mean;
        g_invstd[co] = rsqrtf(var + 1e-5f);
    }
}

// ---------------------------------------------------------------------------
// QKV bf16-split mma.sync GEMM with BN+ReLU fused on the B (feat) tile.
// rows 0..31 = Q, 32..63 = K, 64..319 = V.  K-dim = 256 feat channels.
__global__ __launch_bounds__(256) void qkv_gemm_mma(
    const float* __restrict__ wq, const float* __restrict__ bq,
    const float* __restrict__ wk, const float* __restrict__ bk,
    const float* __restrict__ wv, const float* __restrict__ bv,
    const float* __restrict__ bn_gamma, const float* __restrict__ bn_beta)
{
    __shared__ unsigned short sAh[128][AK], sAl[128][AK];
    __shared__ unsigned short sBh[128][AK], sBl[128][AK];
    __shared__ float sStage[16][128];
    __shared__ float sScale[CO], sShift[CO];

    const int t = threadIdx.x;
    const int wid = t >> 5, lane = t & 31;
    const int g = lane >> 2, tg = lane & 3;
    const int b = blockIdx.z, m0 = blockIdx.y * 128, n0 = blockIdx.x * 128;
    const int wm = (wid & 1) * 64, wn = (wid >> 1) * 32;

    const int ar = t >> 1,  ak  = (t & 1) * 8;
    const int bc = t >> 4,  bn4 = (t & 15) * 8;
    const int tn = t & 127, tk  = (t >> 7) * 8;

    // BN scale/shift into smem (256 threads, one channel each)
    {
        float sc = g_invstd[t] * bn_gamma[t];
        sScale[t] = sc;
        sShift[t] = bn_beta[t] - g_mean[t] * sc;
    }

    float acc[4][4][4];
#pragma unroll
    for (int i = 0; i < 4; i++)
#pragma unroll
        for (int j = 0; j < 4; j++)
#pragma unroll
            for (int r = 0; r < 4; r++) acc[i][j][r] = 0.0f;

    const int mg_a = m0 + ar;
    const float* wrowA = (mg_a < 32)  ? wq + (size_t)mg_a * CO
                       : (mg_a < 64)  ? wk + (size_t)(mg_a - 32) * CO
                       : (mg_a < 320) ? wv + (size_t)(mg_a - 64) * CO
                                      : (const float*)0;

    float4 pA0, pA1, pB0, pB1;
    {
        if (wrowA) {
            pA0 = *(const float4*)(wrowA + ak);
            pA1 = *(const float4*)(wrowA + ak + 4);
        } else {
            pA0 = make_float4(0.f, 0.f, 0.f, 0.f);
            pA1 = pA0;
        }
        const float* pB = g_x + (size_t)(b * CO + bc) * HW + n0 + bn4;
        pB0 = *(const float4*)(pB + 0);
        pB1 = *(const float4*)(pB + 4);
    }

    for (int it = 0; it < CO / 16; it++) {
        __syncthreads();
        {
            uint32_t h, l;
            split_pack(pA0.x, pA0.y, h, l);
            *(uint32_t*)&sAh[ar][ak + 0] = h; *(uint32_t*)&sAl[ar][ak + 0] = l;
            split_pack(pA0.z, pA0.w, h, l);
            *(uint32_t*)&sAh[ar][ak + 2] = h; *(uint32_t*)&sAl[ar][ak + 2] = l;
            split_pack(pA1.x, pA1.y, h, l);
            *(uint32_t*)&sAh[ar][ak + 4] = h; *(uint32_t*)&sAl[ar][ak + 4] = l;
            split_pack(pA1.z, pA1.w, h, l);
            *(uint32_t*)&sAh[ar][ak + 6] = h; *(uint32_t*)&sAl[ar][ak + 6] = l;
        }
        *(float4*)&sStage[bc][bn4 + 0] = pB0;
        *(float4*)&sStage[bc][bn4 + 4] = pB1;
        __syncthreads();
        // BN + ReLU + transpose + split
        {
            int k0 = it * 16;
#pragma unroll
            for (int j = 0; j < 8; j += 2) {
                int ch0 = k0 + tk + j;
                float v0 = fmaxf(sStage[tk + j][tn]     * sScale[ch0]     + sShift[ch0],     0.0f);
                float v1 = fmaxf(sStage[tk + j + 1][tn] * sScale[ch0 + 1] + sShift[ch0 + 1], 0.0f);
                uint32_t h, l;
                split_pack(v0, v1, h, l);
                *(uint32_t*)&sBh[tn][tk + j] = h;
                *(uint32_t*)&sBl[tn][tk + j] = l;
            }
        }
        __syncthreads();
        if (it + 1 < CO / 16) {
            int k0n = (it + 1) * 16;
            if (wrowA) {
                pA0 = *(const float4*)(wrowA + k0n + ak);
                pA1 = *(const float4*)(wrowA + k0n + ak + 4);
            }
            const float* pB = g_x + (size_t)(b * CO + k0n + bc) * HW + n0 + bn4;
            pB0 = *(const float4*)(pB + 0);
            pB1 = *(const float4*)(pB + 4);
        }
#pragma unroll
        for (int pass = 0; pass < 3; pass++) {
            const unsigned short (*A)[AK] = (pass == 2) ? sAl : sAh;
            const unsigned short (*B)[AK] = (pass == 1) ? sBl : sBh;
            uint32_t bf[4][2];
#pragma unroll
            for (int nt = 0; nt < 4; nt++) {
                bf[nt][0] = *(const uint32_t*)&B[wn + nt * 8 + g][2 * tg];
                bf[nt][1] = *(const uint32_t*)&B[wn + nt * 8 + g][2 * tg + 8];
            }
#pragma unroll
            for (int mt = 0; mt < 4; mt++) {
                uint32_t a0 = *(const uint32_t*)&A[wm + mt * 16 + g][2 * tg];
                uint32_t a1 = *(const uint32_t*)&A[wm + mt * 16 + g + 8][2 * tg];
                uint32_t a2 = *(const uint32_t*)&A[wm + mt * 16 + g][2 * tg + 8];
                uint32_t a3 = *(const uint32_t*)&A[wm + mt * 16 + g + 8][2 * tg + 8];
#pragma unroll
                for (int nt = 0; nt < 4; nt++)
                    mma16816(acc[mt][nt], a0, a1, a2, a3, bf[nt][0], bf[nt][1]);
            }
        }
    }

    // writeback with bias + routing (rows mg and mg+8)
#pragma unroll
    for (int mt = 0; mt < 4; mt++) {
#pragma unroll
        for (int half = 0; half < 2; half++) {
            int mg = m0 + wm + mt * 16 + g + half * 8;
            if (mg >= 320) continue;
            float bias; float* dst;
            if (mg < 32)      { bias = bq[mg];      dst = g_q + (size_t)(b * CQ + mg) * HW; }
            else if (mg < 64) { bias = bk[mg - 32]; dst = g_k + (size_t)(b * CQ + mg - 32) * HW; }
            else              { bias = bv[mg - 64]; dst = g_v + (size_t)(b * CO + mg - 64) * HW; }
            dst += n0 + wn + 2 * tg;
#pragma unroll
            for (int nt = 0; nt < 4; nt++)
                *(float2*)(dst + nt * 8) = make_float2(acc[mt][nt][2 * half] + bias,
                                                       acc[mt][nt][2 * half + 1] + bias);
        }
    }
}

// ---------------------------------------------------------------------------
// L2-normalize Q and K over channels per position, accumulate Ksum
__global__ __launch_bounds__(256) void normalize_qk() {
    const int b = blockIdx.y;
    const int n = blockIdx.x * 256 + threadIdx.x;
    const int lane = threadIdx.x & 31;

    {
        float q[CQ];
        float s = 0.0f;
#pragma unroll
        for (int c = 0; c < CQ; c++) {
            q[c] = g_q[(size_t)(b * CQ + c) * HW + n];
            s += q[c] * q[c];
        }
        float sc = 1.0f / fmaxf(sqrtf(s), 1e-6f);
#pragma unroll
        for (int c = 0; c < CQ; c++)
            g_q[(size_t)(b * CQ + c) * HW + n] = q[c] * sc;
    }
    {
        float k[CQ];
        float s = 0.0f;
#pragma unroll
        for (int c = 0; c < CQ; c++) {
            k[c] = g_k[(size_t)(b * CQ + c) * HW + n];
            s += k[c] * k[c];
        }
        float sc = 1.0f / fmaxf(sqrtf(s), 1e-6f);
#pragma unroll
        for (int c = 0; c < CQ; c++) {
            float v = k[c] * sc;
            g_k[(size_t)(b * CQ + c) * HW + n] = v;
            float r = v;
#pragma unroll
            for (int off = 16; off > 0; off >>= 1)
                r += __shfl_down_sync(0xffffffffu, r, off);
            if (lane == 0) atomicAdd(&g_ksum[b * CQ + c], r);
        }
    }
}

// ---------------------------------------------------------------------------
__global__ __launch_bounds__(256) void vsum_kernel() {
    const int c = blockIdx.x;
    const int b = blockIdx.y;
    const int tid = threadIdx.x;
    const float* p = g_v + (size_t)(b * CO + c) * HW;
    float s = 0.0f;
    for (int i = tid; i < HW; i += 256) s += p[i];
    __shared__ float rs[256];
    rs[tid] = s;
    __syncthreads();
    for (int off = 128; off > 0; off >>= 1) {
        if (tid < off) rs[tid] += rs[tid + off];
        __syncthreads();
    }
    if (tid == 0) g_vsum[b * CO + c] = rs[0];
}

// ---------------------------------------------------------------------------
// matrix[b,q,c] = sum_n Kn[b,q,n] * V[b,c,n]  (split-K over n, atomic reduce)
__global__ __launch_bounds__(256) void matrix_kernel() {
    const int b   = blockIdx.z;
    const int c0  = blockIdx.y * 64;
    const int nb0 = blockIdx.x * 512;

    __shared__ float sK[CQ][65];
    __shared__ float sV[64][65];

    const int t  = threadIdx.x;
    const int c  = t & 63;
    const int qg = t >> 6;

    float acc[8];
#pragma unroll
    for (int i = 0; i < 8; i++) acc[i] = 0.0f;

    for (int nb = nb0; nb < nb0 + 512; nb += 64) {
#pragma unroll
        for (int i = 0; i < 8; i++) {
            int idx = t + i * 256;
            int q = idx >> 6, j = idx & 63;
            sK[q][j] = g_k[(size_t)(b * CQ + q) * HW + nb + j];
        }
#pragma unroll
        for (int i = 0; i < 16; i++) {
            int idx = t + i * 256;
            int cc = idx >> 6, j = idx & 63;
            sV[cc][j] = g_v[(size_t)(b * CO + c0 + cc) * HW + nb + j];
        }
        __syncthreads();
#pragma unroll 8
        for (int j = 0; j < 64; j++) {
            float vv = sV[c][j];
#pragma unroll
            for (int i = 0; i < 8; i++)
                acc[i] += sK[qg * 8 + i][j] * vv;
        }
        __syncthreads();
    }
#pragma unroll
    for (int i = 0; i < 8; i++)
        atomicAdd(&g_matrix[(size_t)(b * CQ + qg * 8 + i) * CO + c0 + c], acc[i]);
}

// ---------------------------------------------------------------------------
// Final: out = nan_to_num(gamma * (Vsum + Qn^T matrix) * tailor) + feat
// feat = relu(bn(g_x)) computed inline.
__global__ __launch_bounds__(128) void final_kernel(
    const float* __restrict__ gamma_p,
    const float* __restrict__ bn_gamma, const float* __restrict__ bn_beta,
    float* __restrict__ out)
{
    const int b = blockIdx.y;
    const int n = blockIdx.x * 128 + threadIdx.x;
    const int tid = threadIdx.x;

    __shared__ float sM[CQ][CO];   // 32 KB
    __shared__ float sVs[CO];
    __shared__ float sKs[CQ];
    __shared__ float sScale[CO];
    __shared__ float sShift[CO];

#pragma unroll
    for (int i = 0; i < 64; i++) {
        int idx = tid + i * 128;
        ((float*)sM)[idx] = g_matrix[(size_t)b * CQ * CO + idx];
    }
#pragma unroll
    for (int r = 0; r < 2; r++) {
        int c = tid + r * 128;
        sVs[c] = g_vsum[b * CO + c];
        float scale = g_invstd[c] * bn_gamma[c];
        sScale[c] = scale;
        sShift[c] = bn_beta[c] - g_mean[c] * scale;
    }
    if (tid < CQ) sKs[tid] = g_ksum[b * CQ + tid];
    __syncthreads();

    float qn[CQ];
    float e = 0.0f;
#pragma unroll
    for (int q = 0; q < CQ; q++) {
        qn[q] = g_q[(size_t)(b * CQ + q) * HW + n];
        e += qn[q] * sKs[q];
    }
    const float tailor = 1.0f / fmaxf(NPOS + e, 1e-6f);
    const float gm = *gamma_p;

    for (int c0 = 0; c0 < CO; c0 += 4) {
        float4 a = *(const float4*)&sVs[c0];
#pragma unroll
        for (int q = 0; q < CQ; q++) {
            float4 m4 = *(const float4*)&sM[q][c0];
            a.x += qn[q] * m4.x;
            a.y += qn[q] * m4.y;
            a.z += qn[q] * m4.z;
            a.w += qn[q] * m4.w;
        }
        float r0 = fixnum(gm * a.x * tailor);
        float r1 = fixnum(gm * a.y * tailor);
        float r2 = fixnum(gm * a.z * tailor);
        float r3 = fixnum(gm * a.w * tailor);
        size_t base = (size_t)(b * CO + c0) * HW + n;
        float f0 = fmaxf(g_x[base + 0 * HW] * sScale[c0 + 0] + sShift[c0 + 0], 0.0f);
        float f1 = fmaxf(g_x[base + 1 * HW] * sScale[c0 + 1] + sShift[c0 + 1], 0.0f);
        float f2 = fmaxf(g_x[base + 2 * HW] * sScale[c0 + 2] + sShift[c0 + 2], 0.0f);
        float f3 = fmaxf(g_x[base + 3 * HW] * sScale[c0 + 3] + sShift[c0 + 3], 0.0f);
        out[base + 0 * HW] = r0 + f0;
        out[base + 1 * HW] = r1 + f1;
        out[base + 2 * HW] = r2 + f2;
        out[base + 3 * HW] = r3 + f3;
    }
}

// ---------------------------------------------------------------------------
extern "C" void kernel_launch(void* const* d_in, const int* in_sizes, int n_in,
                              void* d_out, int out_size)
{
    const float* s5 = (const float*)d_in[0];
    const float* s4 = (const float*)d_in[1];
    const float* s3 = (const float*)d_in[2];
    const float* s2 = (const float*)d_in[3];
    const float* w_conv   = (const float*)d_in[4];
    const float* bn_gamma = (const float*)d_in[5];
    const float* bn_beta  = (const float*)d_in[6];
    const float* wq = (const float*)d_in[7];
    const float* bq = (const float*)d_in[8];
    const float* wk = (const float*)d_in[9];
    const float* bk = (const float*)d_in[10];
    const float* wv = (const float*)d_in[11];
    const float* bv = (const float*)d_in[12];
    const float* gamma = (const float*)d_in[13];
    float* out = (float*)d_out;

    zero_kernel<<<64, 256>>>();
    conv_gemm_mma<<<dim3(HW / 128, CO / 128, BB), 256>>>(s5, s4, s3, s2, w_conv);
    bn_stats<<<CO, 512>>>();
    qkv_gemm_mma<<<dim3(HW / 128, 3, BB), 256>>>(wq, bq, wk, bk, wv, bv, bn_gamma, bn_beta);
    normalize_qk<<<dim3(HW / 256, BB), 256>>>();
    vsum_kernel<<<dim3(CO, BB), 256>>>();
    matrix_kernel<<<dim3(32, CO / 64, BB), 256>>>();
    final_kernel<<<dim3(HW / 128, BB), 128>>>(gamma, bn_gamma, bn_beta, out);
}

// round 10
// speedup vs baseline: 2.6033x; 1.2357x over previous
#include <cuda_runtime.h>
#include <cuda_bf16.h>
#include <math.h>
#include <stdint.h>

// Problem constants
#define BB   4
#define CINE 256
#define CIN  1024
#define CO   256
#define HW   16384        // H*W = 128*128
#define CQ   32
#define NPOS 16384.0f

#define AK   24           // padded bf16 row length: 48B rows, 16B-aligned, conflict-free ldmatrix

// dynamic smem layout (bytes)
#define SAH   0                       // 128*48 = 6144
#define SAL   6144
#define SBH   12288
#define SBL   18432
#define STGA  24576                   // 2 x 8192 (128x16 fp32)
#define STGB  40960                   // 2 x 8192 (16x128 fp32)
#define SSC   57344                   // 256 fp32 BN scale
#define SSF   58368                   // 256 fp32 BN shift
#define SMTOT 59392

// Scratch (device globals -- no runtime allocation allowed)
__device__ float g_x[(size_t)BB * CO * HW];   // raw conv output (pre-BN)
__device__ float g_v[(size_t)BB * CO * HW];   // V
__device__ float g_q[BB * CQ * HW];           // Q then Qn
__device__ float g_k[BB * CQ * HW];           // K then Kn
__device__ float g_mean[CO];
__device__ float g_invstd[CO];
__device__ float g_ksum[BB * CQ];
__device__ float g_vsum[BB * CO];
__device__ float g_matrix[BB * CQ * CO];

__device__ __forceinline__ float fixnum(float r) {
    if (isnan(r)) return 0.0f;
    if (isinf(r)) return r > 0.0f ? 1.0f : -1.0f;
    return r;
}

__device__ __forceinline__ uint32_t smem_u32(const void* p) {
    uint32_t a;
    asm("{ .reg .u64 t; cvta.to.shared.u64 t, %1; cvt.u32.u64 %0, t; }"
        : "=r"(a) : "l"(p));
    return a;
}

#define CP_ASYNC(dst, src) \
    asm volatile("cp.async.cg.shared.global [%0], [%1], 16;" :: "r"(dst), "l"(src))
#define CP_COMMIT() asm volatile("cp.async.commit_group;" ::: "memory")
#define CP_WAIT1()  asm volatile("cp.async.wait_group 1;" ::: "memory")
#define CP_WAIT0()  asm volatile("cp.async.wait_group 0;" ::: "memory")

__device__ __forceinline__ void ldm_x4(uint32_t& r0, uint32_t& r1,
                                       uint32_t& r2, uint32_t& r3, uint32_t addr) {
    asm volatile("ldmatrix.sync.aligned.m8n8.x4.shared.b16 {%0,%1,%2,%3}, [%4];"
                 : "=r"(r0), "=r"(r1), "=r"(r2), "=r"(r3) : "r"(addr));
}

// hi/lo bf16 split of two floats, packed as bf16x2 (x -> low 16 bits)
__device__ __forceinline__ void split_pack(float x, float y, uint32_t& h, uint32_t& l) {
    __nv_bfloat162 hb = __floats2bfloat162_rn(x, y);
    h = *reinterpret_cast<uint32_t*>(&hb);
    float rx = x - __bfloat162float(hb.x);
    float ry = y - __bfloat162float(hb.y);
    __nv_bfloat162 lb = __floats2bfloat162_rn(rx, ry);
    l = *reinterpret_cast<uint32_t*>(&lb);
}

// m16n8k16 row.col bf16 MMA, f32 accumulate in-place
__device__ __forceinline__ void mma16816(float* c,
    uint32_t a0, uint32_t a1, uint32_t a2, uint32_t a3,
    uint32_t b0, uint32_t b1)
{
    asm volatile(
        "mma.sync.aligned.m16n8k16.row.col.f32.bf16.bf16.f32 "
        "{%0,%1,%2,%3}, {%4,%5,%6,%7}, {%8,%9}, {%0,%1,%2,%3};"
        : "+f"(c[0]), "+f"(c[1]), "+f"(c[2]), "+f"(c[3])
        : "r"(a0), "r"(a1), "r"(a2), "r"(a3), "r"(b0), "r"(b1));
}

// ---------------------------------------------------------------------------
__global__ void zero_kernel() {
    int tid = blockIdx.x * blockDim.x + threadIdx.x;
    int total = BB * CQ + BB * CQ * CO;
    for (int i = tid; i < total; i += gridDim.x * blockDim.x) {
        if (i < BB * CQ) g_ksum[i] = 0.0f;
        else g_matrix[i - BB * CQ] = 0.0f;
    }
}

// ---------------------------------------------------------------------------
// conv 1x1, bf16-split mma.sync + ldmatrix + cp.async pipeline.
// g_x[b,m,n] = sum_c w[m,c] * fcat[b,c,n].  CTA tile 128x128, k-chunk 16.
__global__ __launch_bounds__(256, 2) void conv_gemm_mma(
    const float* __restrict__ s5, const float* __restrict__ s4,
    const float* __restrict__ s3, const float* __restrict__ s2,
    const float* __restrict__ w)
{
    extern __shared__ char smem[];
    const uint32_t sb = smem_u32(smem);

    const int t = threadIdx.x;
    const int wid = t >> 5, lane = t & 31;
    const int g = lane >> 2, tg = lane & 3;
    const int b = blockIdx.z, m0 = blockIdx.y * 128, n0 = blockIdx.x * 128;
    const int wm = (wid & 1) * 64, wn = (wid >> 1) * 32;

    // split/transpose worker indices
    const int ar = t >> 1,  aks = (t & 1) * 8;    // A split: row ar, k aks..aks+7
    const int tn = t & 127, tk  = (t >> 7) * 8;   // B transpose: col tn, k tk..tk+7

    // ldmatrix addresses (lane-dependent, loop-invariant)
    uint32_t aAh[4], aAl[4];
#pragma unroll
    for (int mt = 0; mt < 4; mt++) {
        int m = wm + mt * 16 + (lane & 15);
        int col = (lane >> 4) * 8;
        aAh[mt] = sb + SAH + (uint32_t)(m * AK + col) * 2;
        aAl[mt] = aAh[mt] + (SAL - SAH);
    }
    uint32_t aBh[2], aBl[2];
#pragma unroll
    for (int p = 0; p < 2; p++) {
        int n = wn + p * 16 + (lane & 7) + ((lane >> 4) << 3);
        int col = ((lane >> 3) & 1) * 8;
        aBh[p] = sb + SBH + (uint32_t)(n * AK + col) * 2;
        aBl[p] = aBh[p] + (SBL - SBH);
    }

    float acc[4][4][4];
#pragma unroll
    for (int i = 0; i < 4; i++)
#pragma unroll
        for (int j = 0; j < 4; j++)
#pragma unroll
            for (int r = 0; r < 4; r++) acc[i][j][r] = 0.0f;

    const int NI = CIN / 16;

    // stage loader (cp.async): 2 A-chunks + 2 B-chunks per thread
    auto issue = [&](int buf, int k0) {
#pragma unroll
        for (int i = 0; i < 2; i++) {
            int idx = t + i * 256;
            int row = idx >> 2, c4 = (idx & 3) * 4;
            const float* gp = w + (size_t)(m0 + row) * CIN + k0 + c4;
            CP_ASYNC(sb + STGA + buf * 8192 + (uint32_t)(row * 16 + c4) * 4, gp);
        }
#pragma unroll
        for (int i = 0; i < 2; i++) {
            int idx = t + i * 256;
            int ch = idx >> 5, n4 = (idx & 31) * 4;
            int c = k0 + ch;
            const float* src = (c < 512) ? (c < 256 ? s5 : s4) : (c < 768 ? s3 : s2);
            CP_ASYNC(sb + STGB + buf * 8192 + (uint32_t)(ch * 128 + n4) * 4,
                     src + (size_t)(b * CINE + (c & 255)) * HW + n0 + n4);
        }
    };

    issue(0, 0);
    CP_COMMIT();

    for (int it = 0; it < NI; it++) {
        const int buf = it & 1;
        if (it + 1 < NI) { issue(buf ^ 1, (it + 1) * 16); CP_COMMIT(); CP_WAIT1(); }
        else CP_WAIT0();
        __syncthreads();   // stage[buf] complete for all threads; prev mma done

        // A split: stageA -> sAh/sAl
        {
            const float4* srcp = (const float4*)(smem + STGA + buf * 8192 + (ar * 16 + aks) * 4);
            float4 v0 = srcp[0], v1 = srcp[1];
            uint32_t h, l;
            char* ph = smem + SAH + (ar * AK + aks) * 2;
            char* pl = smem + SAL + (ar * AK + aks) * 2;
            split_pack(v0.x, v0.y, h, l); *(uint32_t*)(ph + 0) = h; *(uint32_t*)(pl + 0) = l;
            split_pack(v0.z, v0.w, h, l); *(uint32_t*)(ph + 4) = h; *(uint32_t*)(pl + 4) = l;
            split_pack(v1.x, v1.y, h, l); *(uint32_t*)(ph + 8) = h; *(uint32_t*)(pl + 8) = l;
            split_pack(v1.z, v1.w, h, l); *(uint32_t*)(ph + 12) = h; *(uint32_t*)(pl + 12) = l;
        }
        // B transpose+split: stageB -> sBh/sBl
        {
            const float* stg = (const float*)(smem + STGB + buf * 8192);
            char* ph = smem + SBH + (tn * AK + tk) * 2;
            char* pl = smem + SBL + (tn * AK + tk) * 2;
#pragma unroll
            for (int j = 0; j < 8; j += 2) {
                float v0 = stg[(tk + j) * 128 + tn];
                float v1 = stg[(tk + j + 1) * 128 + tn];
                uint32_t h, l;
                split_pack(v0, v1, h, l);
                *(uint32_t*)(ph + j * 2) = h;
                *(uint32_t*)(pl + j * 2) = l;
            }
        }
        __syncthreads();

        // fragments via ldmatrix; pass order reuses Ah (p0,p1) and Bh (p0,p2)
        uint32_t af[4][4], bh[4][2], bl[4][2];
        ldm_x4(bh[0][0], bh[0][1], bh[1][0], bh[1][1], aBh[0]);
        ldm_x4(bh[2][0], bh[2][1], bh[3][0], bh[3][1], aBh[1]);
#pragma unroll
        for (int mt = 0; mt < 4; mt++)
            ldm_x4(af[mt][0], af[mt][1], af[mt][2], af[mt][3], aAh[mt]);
#pragma unroll
        for (int mt = 0; mt < 4; mt++)
#pragma unroll
            for (int nt = 0; nt < 4; nt++)
                mma16816(acc[mt][nt], af[mt][0], af[mt][1], af[mt][2], af[mt][3],
                         bh[nt][0], bh[nt][1]);
        ldm_x4(bl[0][0], bl[0][1], bl[1][0], bl[1][1], aBl[0]);
        ldm_x4(bl[2][0], bl[2][1], bl[3][0], bl[3][1], aBl[1]);
#pragma unroll
        for (int mt = 0; mt < 4; mt++)
#pragma unroll
            for (int nt = 0; nt < 4; nt++)
                mma16816(acc[mt][nt], af[mt][0], af[mt][1], af[mt][2], af[mt][3],
                         bl[nt][0], bl[nt][1]);
#pragma unroll
        for (int mt = 0; mt < 4; mt++)
            ldm_x4(af[mt][0], af[mt][1], af[mt][2], af[mt][3], aAl[mt]);
#pragma unroll
        for (int mt = 0; mt < 4; mt++)
#pragma unroll
            for (int nt = 0; nt < 4; nt++)
                mma16816(acc[mt][nt], af[mt][0], af[mt][1], af[mt][2], af[mt][3],
                         bh[nt][0], bh[nt][1]);
    }

    // writeback
#pragma unroll
    for (int mt = 0; mt < 4; mt++) {
        int m = m0 + wm + mt * 16 + g;
        float* base = g_x + (size_t)(b * CO + m) * HW + n0 + wn + 2 * tg;
#pragma unroll
        for (int nt = 0; nt < 4; nt++) {
            float* p = base + nt * 8;
            *(float2*)p = make_float2(acc[mt][nt][0], acc[mt][nt][1]);
            *(float2*)(p + 8 * HW) = make_float2(acc[mt][nt][2], acc[mt][nt][3]);
        }
    }
}

// ---------------------------------------------------------------------------
// BN statistics over raw conv output: one block per channel
__global__ __launch_bounds__(512) void bn_stats() {
    const int co = blockIdx.x;
    const int tid = threadIdx.x;
    float s = 0.0f, ss = 0.0f;
    for (int b = 0; b < BB; b++) {
        const float* p = g_x + (size_t)(b * CO + co) * HW;
        for (int i = tid; i < HW; i += 512) {
            float v = p[i];
            s += v;
            ss += v * v;
        }
    }
    __shared__ float rs[512], rss[512];
    rs[tid] = s; rss[tid] = ss;
    __syncthreads();
    for (int off = 256; off > 0; off >>= 1) {
        if (tid < off) { rs[tid] += rs[tid + off]; rss[tid] += rss[tid + off]; }
        __syncthreads();
    }
    if (tid == 0) {
        const float cnt = (float)(BB * HW);
        float mean = rs[0] / cnt;
        float var  = rss[0] / cnt - mean * mean;
        g_mean[co]   = mean;
        g_invstd[co] = rsqrtf(var + 1e-5f);
    }
}

// ---------------------------------------------------------------------------
// QKV GEMM, same pipeline; BN+ReLU fused into B transpose stage.
// rows 0..31 = Q, 32..63 = K, 64..319 = V.  K-dim = 256 feat channels.
__global__ __launch_bounds__(256, 2) void qkv_gemm_mma(
    const float* __restrict__ wq, const float* __restrict__ bq,
    const float* __restrict__ wk, const float* __restrict__ bk,
    const float* __restrict__ wv, const float* __restrict__ bv,
    const float* __restrict__ bn_gamma, const float* __restrict__ bn_beta)
{
    extern __shared__ char smem[];
    const uint32_t sb = smem_u32(smem);

    const int t = threadIdx.x;
    const int wid = t >> 5, lane = t & 31;
    const int g = lane >> 2, tg = lane & 3;
    const int b = blockIdx.z, m0 = blockIdx.y * 128, n0 = blockIdx.x * 128;
    const int wm = (wid & 1) * 64, wn = (wid >> 1) * 32;

    const int ar = t >> 1,  aks = (t & 1) * 8;
    const int tn = t & 127, tk  = (t >> 7) * 8;

    // BN scale/shift into smem (one channel per thread)
    {
        float sc = g_invstd[t] * bn_gamma[t];
        ((float*)(smem + SSC))[t] = sc;
        ((float*)(smem + SSF))[t] = bn_beta[t] - g_mean[t] * sc;
    }
    // pre-zero invalid A stage rows (rows >= 64 of the m0=256 tile), both buffers
    if (m0 == 256) {
#pragma unroll
        for (int buf = 0; buf < 2; buf++) {
            float4* z = (float4*)(smem + STGA + buf * 8192 + 4096);
            for (int i = t; i < 256; i += 256) z[i] = make_float4(0.f, 0.f, 0.f, 0.f);
        }
    }

    uint32_t aAh[4], aAl[4];
#pragma unroll
    for (int mt = 0; mt < 4; mt++) {
        int m = wm + mt * 16 + (lane & 15);
        int col = (lane >> 4) * 8;
        aAh[mt] = sb + SAH + (uint32_t)(m * AK + col) * 2;
        aAl[mt] = aAh[mt] + (SAL - SAH);
    }
    uint32_t aBh[2], aBl[2];
#pragma unroll
    for (int p = 0; p < 2; p++) {
        int n = wn + p * 16 + (lane & 7) + ((lane >> 4) << 3);
        int col = ((lane >> 3) & 1) * 8;
        aBh[p] = sb + SBH + (uint32_t)(n * AK + col) * 2;
        aBl[p] = aBh[p] + (SBL - SBH);
    }

    float acc[4][4][4];
#pragma unroll
    for (int i = 0; i < 4; i++)
#pragma unroll
        for (int j = 0; j < 4; j++)
#pragma unroll
            for (int r = 0; r < 4; r++) acc[i][j][r] = 0.0f;

    const int NI = CO / 16;

    auto issue = [&](int buf, int k0) {
#pragma unroll
        for (int i = 0; i < 2; i++) {
            int idx = t + i * 256;
            int row = idx >> 2, c4 = (idx & 3) * 4;
            int mg = m0 + row;
            if (mg < 320) {
                const float* wrow = (mg < 32) ? wq + (size_t)mg * CO
                                  : (mg < 64) ? wk + (size_t)(mg - 32) * CO
                                              : wv + (size_t)(mg - 64) * CO;
                CP_ASYNC(sb + STGA + buf * 8192 + (uint32_t)(row * 16 + c4) * 4,
                         wrow + k0 + c4);
            }
        }
#pragma unroll
        for (int i = 0; i < 2; i++) {
            int idx = t + i * 256;
            int ch = idx >> 5, n4 = (idx & 31) * 4;
            CP_ASYNC(sb + STGB + buf * 8192 + (uint32_t)(ch * 128 + n4) * 4,
                     g_x + (size_t)(b * CO + k0 + ch) * HW + n0 + n4);
        }
    };

    issue(0, 0);
    CP_COMMIT();

    for (int it = 0; it < NI; it++) {
        const int buf = it & 1;
        if (it + 1 < NI) { issue(buf ^ 1, (it + 1) * 16); CP_COMMIT(); CP_WAIT1(); }
        else CP_WAIT0();
        __syncthreads();

        // A split
        {
            const float4* srcp = (const float4*)(smem + STGA + buf * 8192 + (ar * 16 + aks) * 4);
            float4 v0 = srcp[0], v1 = srcp[1];
            uint32_t h, l;
            char* ph = smem + SAH + (ar * AK + aks) * 2;
            char* pl = smem + SAL + (ar * AK + aks) * 2;
            split_pack(v0.x, v0.y, h, l); *(uint32_t*)(ph + 0) = h; *(uint32_t*)(pl + 0) = l;
            split_pack(v0.z, v0.w, h, l); *(uint32_t*)(ph + 4) = h; *(uint32_t*)(pl + 4) = l;
            split_pack(v1.x, v1.y, h, l); *(uint32_t*)(ph + 8) = h; *(uint32_t*)(pl + 8) = l;
            split_pack(v1.z, v1.w, h, l); *(uint32_t*)(ph + 12) = h; *(uint32_t*)(pl + 12) = l;
        }
        // B: BN + ReLU + transpose + split
        {
            const int k0 = it * 16;
            const float* stg = (const float*)(smem + STGB + buf * 8192);
            const float* ssc = (const float*)(smem + SSC);
            const float* ssf = (const float*)(smem + SSF);
            char* ph = smem + SBH + (tn * AK + tk) * 2;
            char* pl = smem + SBL + (tn * AK + tk) * 2;
#pragma unroll
            for (int j = 0; j < 8; j += 2) {
                int ch0 = k0 + tk + j;
                float v0 = fmaxf(stg[(tk + j) * 128 + tn]     * ssc[ch0]     + ssf[ch0],     0.0f);
                float v1 = fmaxf(stg[(tk + j + 1) * 128 + tn] * ssc[ch0 + 1] + ssf[ch0 + 1], 0.0f);
                uint32_t h, l;
                split_pack(v0, v1, h, l);
                *(uint32_t*)(ph + j * 2) = h;
                *(uint32_t*)(pl + j * 2) = l;
            }
        }
        __syncthreads();

        uint32_t af[4][4], bh[4][2], bl[4][2];
        ldm_x4(bh[0][0], bh[0][1], bh[1][0], bh[1][1], aBh[0]);
        ldm_x4(bh[2][0], bh[2][1], bh[3][0], bh[3][1], aBh[1]);
#pragma unroll
        for (int mt = 0; mt < 4; mt++)
            ldm_x4(af[mt][0], af[mt][1], af[mt][2], af[mt][3], aAh[mt]);
#pragma unroll
        for (int mt = 0; mt < 4; mt++)
#pragma unroll
            for (int nt = 0; nt < 4; nt++)
                mma16816(acc[mt][nt], af[mt][0], af[mt][1], af[mt][2], af[mt][3],
                         bh[nt][0], bh[nt][1]);
        ldm_x4(bl[0][0], bl[0][1], bl[1][0], bl[1][1], aBl[0]);
        ldm_x4(bl[2][0], bl[2][1], bl[3][0], bl[3][1], aBl[1]);
#pragma unroll
        for (int mt = 0; mt < 4; mt++)
#pragma unroll
            for (int nt = 0; nt < 4; nt++)
                mma16816(acc[mt][nt], af[mt][0], af[mt][1], af[mt][2], af[mt][3],
                         bl[nt][0], bl[nt][1]);
#pragma unroll
        for (int mt = 0; mt < 4; mt++)
            ldm_x4(af[mt][0], af[mt][1], af[mt][2], af[mt][3], aAl[mt]);
#pragma unroll
        for (int mt = 0; mt < 4; mt++)
#pragma unroll
            for (int nt = 0; nt < 4; nt++)
                mma16816(acc[mt][nt], af[mt][0], af[mt][1], af[mt][2], af[mt][3],
                         bh[nt][0], bh[nt][1]);
    }

    // writeback with bias + routing (rows mg and mg+8)
#pragma unroll
    for (int mt = 0; mt < 4; mt++) {
#pragma unroll
        for (int half = 0; half < 2; half++) {
            int mg = m0 + wm + mt * 16 + g + half * 8;
            if (mg >= 320) continue;
            float bias; float* dst;
            if (mg < 32)      { bias = bq[mg];      dst = g_q + (size_t)(b * CQ + mg) * HW; }
            else if (mg < 64) { bias = bk[mg - 32]; dst = g_k + (size_t)(b * CQ + mg - 32) * HW; }
            else              { bias = bv[mg - 64]; dst = g_v + (size_t)(b * CO + mg - 64) * HW; }
            dst += n0 + wn + 2 * tg;
#pragma unroll
            for (int nt = 0; nt < 4; nt++)
                *(float2*)(dst + nt * 8) = make_float2(acc[mt][nt][2 * half] + bias,
                                                       acc[mt][nt][2 * half + 1] + bias);
        }
    }
}

// ---------------------------------------------------------------------------
// L2-normalize Q and K over channels per position, accumulate Ksum
__global__ __launch_bounds__(256) void normalize_qk() {
    const int b = blockIdx.y;
    const int n = blockIdx.x * 256 + threadIdx.x;
    const int lane = threadIdx.x & 31;

    {
        float q[CQ];
        float s = 0.0f;
#pragma unroll
        for (int c = 0; c < CQ; c++) {
            q[c] = g_q[(size_t)(b * CQ + c) * HW + n];
            s += q[c] * q[c];
        }
        float sc = 1.0f / fmaxf(sqrtf(s), 1e-6f);
#pragma unroll
        for (int c = 0; c < CQ; c++)
            g_q[(size_t)(b * CQ + c) * HW + n] = q[c] * sc;
    }
    {
        float k[CQ];
        float s = 0.0f;
#pragma unroll
        for (int c = 0; c < CQ; c++) {
            k[c] = g_k[(size_t)(b * CQ + c) * HW + n];
            s += k[c] * k[c];
        }
        float sc = 1.0f / fmaxf(sqrtf(s), 1e-6f);
#pragma unroll
        for (int c = 0; c < CQ; c++) {
            float v = k[c] * sc;
            g_k[(size_t)(b * CQ + c) * HW + n] = v;
            float r = v;
#pragma unroll
            for (int off = 16; off > 0; off >>= 1)
                r += __shfl_down_sync(0xffffffffu, r, off);
            if (lane == 0) atomicAdd(&g_ksum[b * CQ + c], r);
        }
    }
}

// ---------------------------------------------------------------------------
__global__ __launch_bounds__(256) void vsum_kernel() {
    const int c = blockIdx.x;
    const int b = blockIdx.y;
    const int tid = threadIdx.x;
    const float* p = g_v + (size_t)(b * CO + c) * HW;
    float s = 0.0f;
    for (int i = tid; i < HW; i += 256) s += p[i];
    __shared__ float rs[256];
    rs[tid] = s;
    __syncthreads();
    for (int off = 128; off > 0; off >>= 1) {
        if (tid < off) rs[tid] += rs[tid + off];
        __syncthreads();
    }
    if (tid == 0) g_vsum[b * CO + c] = rs[0];
}

// ---------------------------------------------------------------------------
// matrix[b,q,c] = sum_n Kn[b,q,n] * V[b,c,n]  (split-K over n, atomic reduce)
__global__ __launch_bounds__(256) void matrix_kernel() {
    const int b   = blockIdx.z;
    const int c0  = blockIdx.y * 64;
    const int nb0 = blockIdx.x * 512;

    __shared__ float sK[CQ][65];
    __shared__ float sV[64][65];

    const int t  = threadIdx.x;
    const int c  = t & 63;
    const int qg = t >> 6;

    float acc[8];
#pragma unroll
    for (int i = 0; i < 8; i++) acc[i] = 0.0f;

    for (int nb = nb0; nb < nb0 + 512; nb += 64) {
#pragma unroll
        for (int i = 0; i < 8; i++) {
            int idx = t + i * 256;
            int q = idx >> 6, j = idx & 63;
            sK[q][j] = g_k[(size_t)(b * CQ + q) * HW + nb + j];
        }
#pragma unroll
        for (int i = 0; i < 16; i++) {
            int idx = t + i * 256;
            int cc = idx >> 6, j = idx & 63;
            sV[cc][j] = g_v[(size_t)(b * CO + c0 + cc) * HW + nb + j];
        }
        __syncthreads();
#pragma unroll 8
        for (int j = 0; j < 64; j++) {
            float vv = sV[c][j];
#pragma unroll
            for (int i = 0; i < 8; i++)
                acc[i] += sK[qg * 8 + i][j] * vv;
        }
        __syncthreads();
    }
#pragma unroll
    for (int i = 0; i < 8; i++)
        atomicAdd(&g_matrix[(size_t)(b * CQ + qg * 8 + i) * CO + c0 + c], acc[i]);
}

// ---------------------------------------------------------------------------
// Final: out = nan_to_num(gamma * (Vsum + Qn^T matrix) * tailor) + feat
// feat = relu(bn(g_x)) computed inline.
__global__ __launch_bounds__(128) void final_kernel(
    const float* __restrict__ gamma_p,
    const float* __restrict__ bn_gamma, const float* __restrict__ bn_beta,
    float* __restrict__ out)
{
    const int b = blockIdx.y;
    const int n = blockIdx.x * 128 + threadIdx.x;
    const int tid = threadIdx.x;

    __shared__ float sM[CQ][CO];   // 32 KB
    __shared__ float sVs[CO];
    __shared__ float sKs[CQ];
    __shared__ float sScale[CO];
    __shared__ float sShift[CO];

#pragma unroll
    for (int i = 0; i < 64; i++) {
        int idx = tid + i * 128;
        ((float*)sM)[idx] = g_matrix[(size_t)b * CQ * CO + idx];
    }
#pragma unroll
    for (int r = 0; r < 2; r++) {
        int c = tid + r * 128;
        sVs[c] = g_vsum[b * CO + c];
        float scale = g_invstd[c] * bn_gamma[c];
        sScale[c] = scale;
        sShift[c] = bn_beta[c] - g_mean[c] * scale;
    }
    if (tid < CQ) sKs[tid] = g_ksum[b * CQ + tid];
    __syncthreads();

    float qn[CQ];
    float e = 0.0f;
#pragma unroll
    for (int q = 0; q < CQ; q++) {
        qn[q] = g_q[(size_t)(b * CQ + q) * HW + n];
        e += qn[q] * sKs[q];
    }
    const float tailor = 1.0f / fmaxf(NPOS + e, 1e-6f);
    const float gm = *gamma_p;

    for (int c0 = 0; c0 < CO; c0 += 4) {
        float4 a = *(const float4*)&sVs[c0];
#pragma unroll
        for (int q = 0; q < CQ; q++) {
            float4 m4 = *(const float4*)&sM[q][c0];
            a.x += qn[q] * m4.x;
            a.y += qn[q] * m4.y;
            a.z += qn[q] * m4.z;
            a.w += qn[q] * m4.w;
        }
        float r0 = fixnum(gm * a.x * tailor);
        float r1 = fixnum(gm * a.y * tailor);
        float r2 = fixnum(gm * a.z * tailor);
        float r3 = fixnum(gm * a.w * tailor);
        size_t base = (size_t)(b * CO + c0) * HW + n;
        float f0 = fmaxf(g_x[base + 0 * HW] * sScale[c0 + 0] + sShift[c0 + 0], 0.0f);
        float f1 = fmaxf(g_x[base + 1 * HW] * sScale[c0 + 1] + sShift[c0 + 1], 0.0f);
        float f2 = fmaxf(g_x[base + 2 * HW] * sScale[c0 + 2] + sShift[c0 + 2], 0.0f);
        float f3 = fmaxf(g_x[base + 3 * HW] * sScale[c0 + 3] + sShift[c0 + 3], 0.0f);
        out[base + 0 * HW] = r0 + f0;
        out[base + 1 * HW] = r1 + f1;
        out[base + 2 * HW] = r2 + f2;
        out[base + 3 * HW] = r3 + f3;
    }
}

// ---------------------------------------------------------------------------
extern "C" void kernel_launch(void* const* d_in, const int* in_sizes, int n_in,
                              void* d_out, int out_size)
{
    const float* s5 = (const float*)d_in[0];
    const float* s4 = (const float*)d_in[1];
    const float* s3 = (const float*)d_in[2];
    const float* s2 = (const float*)d_in[3];
    const float* w_conv   = (const float*)d_in[4];
    const float* bn_gamma = (const float*)d_in[5];
    const float* bn_beta  = (const float*)d_in[6];
    const float* wq = (const float*)d_in[7];
    const float* bq = (const float*)d_in[8];
    const float* wk = (const float*)d_in[9];
    const float* bk = (const float*)d_in[10];
    const float* wv = (const float*)d_in[11];
    const float* bv = (const float*)d_in[12];
    const float* gamma = (const float*)d_in[13];
    float* out = (float*)d_out;

    static int attr_done = 0;
    if (!attr_done) {
        cudaFuncSetAttribute(conv_gemm_mma, cudaFuncAttributeMaxDynamicSharedMemorySize, SMTOT);
        cudaFuncSetAttribute(qkv_gemm_mma,  cudaFuncAttributeMaxDynamicSharedMemorySize, SMTOT);
        attr_done = 1;
    }

    zero_kernel<<<64, 256>>>();
    conv_gemm_mma<<<dim3(HW / 128, CO / 128, BB), 256, SMTOT>>>(s5, s4, s3, s2, w_conv);
    bn_stats<<<CO, 512>>>();
    qkv_gemm_mma<<<dim3(HW / 128, 3, BB), 256, SMTOT>>>(wq, bq, wk, bk, wv, bv, bn_gamma, bn_beta);
    normalize_qk<<<dim3(HW / 256, BB), 256>>>();
    vsum_kernel<<<dim3(CO, BB), 256>>>();
    matrix_kernel<<<dim3(32, CO / 64, BB), 256>>>();
    final_kernel<<<dim3(HW / 128, BB), 128>>>(gamma, bn_gamma, bn_beta, out);
}